// round 10
// baseline (speedup 1.0000x reference)
#include <cuda_runtime.h>
#include <math.h>
#include <stdint.h>

// Problem constants
#define T_TOK   4096      // B*S = 2*2048
#define HDIM    1024
#define IDIM    4096
#define NEXP    8
#define MAXSLOT 9216      // 8192 pairs + per-expert pad to 128
#define MAXMB   72        // max m-blocks of 128 rows

// ---------------- static scratch (no runtime allocation) ----------------
__device__ float g_hdn [(size_t)MAXSLOT * IDIM];       // 151 MB  gate/up output (tf32-rounded)
__device__ float g_pout[(size_t)MAXSLOT * HDIM];       // 37.7 MB down output
__device__ float g_xr  [(size_t)T_TOK * HDIM];         // 16.8 MB tf32-rounded x
__device__ float g_wgT [(size_t)NEXP * HDIM * IDIM];   // 134 MB  wg^T  [E][I][H], tf32
__device__ float g_wuT [(size_t)NEXP * HDIM * IDIM];   // 134 MB  wu^T  [E][I][H], tf32
__device__ float g_wdT [(size_t)NEXP * HDIM * IDIM];   // 134 MB  wd^T  [E][H][I], tf32
__device__ int   g_perm[MAXSLOT];                      // slot -> token (-1 = pad)
__device__ int   g_tok2slot[T_TOK * 2];
__device__ float g_tokw   [T_TOK * 2];
__device__ int   g_tokidx [T_TOK * 2];
__device__ int   g_counts [NEXP];
__device__ float g_load   [NEXP];
__device__ int   g_cursor [NEXP];
__device__ int   g_off    [NEXP];
__device__ int2  g_mblocks[80];
__device__ int   g_nmblocks;

// ---------------- PTX helpers ----------------
__device__ __forceinline__ uint32_t f2tf32(float f) {
    uint32_t u;
    asm volatile("cvt.rna.tf32.f32 %0, %1;\n" : "=r"(u) : "f"(f));
    return u;
}
__device__ __forceinline__ float tf32r(float f) { return __uint_as_float(f2tf32(f)); }

__device__ __forceinline__ void mma8(float* d, const uint32_t* a, uint32_t b0, uint32_t b1) {
    asm volatile(
        "mma.sync.aligned.m16n8k8.row.col.f32.tf32.tf32.f32 "
        "{%0,%1,%2,%3}, {%4,%5,%6,%7}, {%8,%9}, {%0,%1,%2,%3};\n"
        : "+f"(d[0]), "+f"(d[1]), "+f"(d[2]), "+f"(d[3])
        : "r"(a[0]), "r"(a[1]), "r"(a[2]), "r"(a[3]), "r"(b0), "r"(b1));
}

__device__ __forceinline__ void cp16(uint32_t dst, const void* src, int bytes) {
    asm volatile("cp.async.cg.shared.global [%0], [%1], 16, %2;\n"
                 :: "r"(dst), "l"(src), "r"(bytes));
}
__device__ __forceinline__ void cp_commit() { asm volatile("cp.async.commit_group;\n"); }
template <int N>
__device__ __forceinline__ void cp_wait() { asm volatile("cp.async.wait_group %0;\n" :: "n"(N)); }

// ---------------- kernel 1: init ----------------
__global__ void moe_init() {
    int tid = threadIdx.x;
    for (int i = tid; i < MAXSLOT; i += 256) g_perm[i] = -1;
    if (tid < NEXP) { g_counts[tid] = 0; g_load[tid] = 0.f; g_cursor[tid] = 0; }
}

// ---------------- kernel 2: router (exact fp32) ----------------
__global__ void moe_router(const float* __restrict__ x, const float* __restrict__ gw) {
    const int warp = threadIdx.x >> 5;
    const int lane = threadIdx.x & 31;
    const int t = blockIdx.x * 8 + warp;

    const int e   = lane & 7;
    const int seg = lane >> 3;
    const float* xr  = x  + (size_t)t * HDIM + seg * 256;
    const float* gwp = gw + (size_t)(seg * 256) * NEXP + e;
    float acc = 0.f;
    #pragma unroll 8
    for (int j = 0; j < 256; j++) acc += xr[j] * gwp[j * NEXP];
    acc += __shfl_xor_sync(0xffffffffu, acc, 8);
    acc += __shfl_xor_sync(0xffffffffu, acc, 16);

    float lg[8];
    #pragma unroll
    for (int i = 0; i < 8; i++) lg[i] = __shfl_sync(0xffffffffu, acc, i);

    if (lane == 0) {
        float m = lg[0];
        #pragma unroll
        for (int i = 1; i < 8; i++) m = fmaxf(m, lg[i]);
        float p[8], s = 0.f;
        #pragma unroll
        for (int i = 0; i < 8; i++) { p[i] = expf(lg[i] - m); s += p[i]; }
        float inv = 1.f / s;
        #pragma unroll
        for (int i = 0; i < 8; i++) p[i] *= inv;
        int i1 = 0;
        #pragma unroll
        for (int i = 1; i < 8; i++) if (p[i] > p[i1]) i1 = i;
        int i2 = (i1 == 0) ? 1 : 0;
        #pragma unroll
        for (int i = 0; i < 8; i++) if (i != i1 && p[i] > p[i2]) i2 = i;
        float denom = p[i1] + p[i2];
        g_tokidx[2 * t]     = i1;
        g_tokidx[2 * t + 1] = i2;
        g_tokw[2 * t]       = p[i1] / denom;
        g_tokw[2 * t + 1]   = p[i2] / denom;
        atomicAdd(&g_counts[i1], 1);
        atomicAdd(&g_counts[i2], 1);
        atomicAdd(&g_load[i1], p[i1]);
        atomicAdd(&g_load[i2], p[i2]);
    }
}

// ---------------- kernel 3: scheduler + aux loss ----------------
__global__ void moe_sched(float* aux_out, int has_aux) {
    if (threadIdx.x == 0) {
        int off = 0, nm = 0;
        for (int e = 0; e < NEXP; e++) {
            g_off[e] = off;
            int nb = (g_counts[e] + 127) >> 7;
            for (int b = 0; b < nb; b++) g_mblocks[nm++] = make_int2(off + b * 128, e);
            off += nb << 7;
        }
        g_nmblocks = nm;
        if (has_aux) {
            float aux = 0.f;
            for (int e = 0; e < NEXP; e++)
                aux += (g_load[e] / (float)T_TOK) * ((float)g_counts[e] / (float)(T_TOK * 2));
            *aux_out = aux * (float)NEXP * 0.001f;
        }
    }
}

// ---------------- kernel 4: scatter ----------------
__global__ void moe_scatter() {
    int t = blockIdx.x * 256 + threadIdx.x;
    if (t < T_TOK) {
        #pragma unroll
        for (int k = 0; k < 2; k++) {
            int e = g_tokidx[2 * t + k];
            int pos = atomicAdd(&g_cursor[e], 1);
            int slot = g_off[e] + pos;
            g_perm[slot] = t;
            g_tok2slot[2 * t + k] = slot;
        }
    }
}

// ---------------- prep: round x to tf32 (writes g_xr, device-side symbol) ----------------
__global__ void prep_round_x(const float* __restrict__ x) {
    size_t i = (size_t)blockIdx.x * 1024 + threadIdx.x * 4;
    float4 v = *(const float4*)(x + i);
    v.x = tf32r(v.x); v.y = tf32r(v.y); v.z = tf32r(v.z); v.w = tf32r(v.w);
    *(float4*)(g_xr + i) = v;
}

// ---------------- prep: transpose + round weights ----------------
// in [E][R][C] -> g_w?T [E][C][R], tf32-rounded. block (32,8), 32x32 tiles.
// which: 0 -> g_wgT, 1 -> g_wuT, 2 -> g_wdT   (selected in DEVICE code)
template <int R, int C>
__global__ void prep_transpose(const float* __restrict__ in, int which) {
    __shared__ float tile[32][33];
    float* outg = (which == 0) ? g_wgT : (which == 1) ? g_wuT : g_wdT;
    const int e = blockIdx.z;
    const float* ip = in + (size_t)e * R * C;
    float* op = outg + (size_t)e * R * C;
    const int x = blockIdx.x * 32 + threadIdx.x;
    const int y0 = blockIdx.y * 32;
    #pragma unroll
    for (int j = threadIdx.y; j < 32; j += 8)
        tile[j][threadIdx.x] = tf32r(ip[(size_t)(y0 + j) * C + x]);
    __syncthreads();
    const int x2 = y0 + threadIdx.x;
    const int y2 = blockIdx.x * 32;
    #pragma unroll
    for (int j = threadIdx.y; j < 32; j += 8)
        op[(size_t)(y2 + j) * R + x2] = tile[threadIdx.x][j];
}

// ---------------- legacy-mma tf32 GEMM ----------------
// All operands pre-rounded to tf32 -> NO cvt in the inner loop.
// All scratch pointers resolved in DEVICE code (g_* are __device__ symbols).
// NMATS==2: A = g_xr gathered via g_perm; B0/B1 = g_wgT/g_wuT [N][K]; out = tf32(silu(g)*u) -> g_hdn
// NMATS==1: A = g_hdn slot rows;          B0 = g_wdT [N][K];          out -> g_pout (fp32)
// CTA 128(M) x 128(N per matrix), BK=32, 256 threads, warp tile 64x32, S-stage cp.async.
template <int NMATS, int KDIM, int NDIM, int S>
__global__ void __launch_bounds__(256, 1)
gemm_mma()
{
    constexpr int RS = 36;                       // padded row stride (floats) -> conflict-free
    constexpr int TILE_F  = 128 * RS;            // floats per 128x32 tile
    constexpr int STAGE_F = (1 + NMATS) * TILE_F;
    constexpr int KT = KDIM / 32;

    const int mb = blockIdx.y;
    if (mb >= g_nmblocks) return;
    const int row0 = g_mblocks[mb].x;
    const int e    = g_mblocks[mb].y;
    const int n0   = blockIdx.x * 128;

    const float* Ag   = (NMATS == 2) ? g_xr : g_hdn;
    const float* B0   = ((NMATS == 2) ? g_wgT : g_wdT) + (size_t)e * KDIM * NDIM;
    const float* B1   = g_wuT + (size_t)e * KDIM * NDIM;   // used only when NMATS==2
    float*       Outg = (NMATS == 2) ? g_hdn : g_pout;

    extern __shared__ float smf[];
    const uint32_t smb = (uint32_t)__cvta_generic_to_shared(smf);

    const int tid  = threadIdx.x;
    const int lane = tid & 31;
    const int wid  = tid >> 5;
    const int wm = wid & 1;      // M half (64 rows)
    const int wn = wid >> 1;     // N quarter (32 cols)
    const int lr = lane >> 2;    // 0..7
    const int lc = lane & 3;     // 0..3

    // ---- loaders: per thread 4 x 16B chunks per 128x32 tile ----
    const float* asrc[4]; int alen[4]; uint32_t adst[4]; uint32_t brel[4];
    const float* b0src[4]; const float* b1src[4];
    #pragma unroll
    for (int i = 0; i < 4; i++) {
        const int c = tid + 256 * i;
        const int r = c >> 3;        // 0..127
        const int kc = c & 7;        // 16B chunk in 128B row
        if (NMATS == 2) {
            const int g = g_perm[row0 + r];
            asrc[i] = (g >= 0) ? (Ag + (size_t)g * KDIM + kc * 4) : Ag;
            alen[i] = (g >= 0) ? 16 : 0;
        } else {
            asrc[i] = Ag + (size_t)(row0 + r) * KDIM + kc * 4;
            alen[i] = 16;
        }
        const uint32_t off = (uint32_t)((r * RS + kc * 4) * 4);
        adst[i] = smb + off;
        brel[i] = off;
        b0src[i] = B0 + (size_t)(n0 + r) * KDIM + kc * 4;
        if (NMATS == 2) b1src[i] = B1 + (size_t)(n0 + r) * KDIM + kc * 4;
    }

    auto load_chunk = [&](int ch) {
        const uint32_t so = (uint32_t)((ch % S) * STAGE_F * 4);
        const int k0 = ch * 32;
        #pragma unroll
        for (int i = 0; i < 4; i++) cp16(adst[i] + so, asrc[i] + k0, alen[i]);
        #pragma unroll
        for (int i = 0; i < 4; i++) cp16(smb + TILE_F * 4 + brel[i] + so, b0src[i] + k0, 16);
        if (NMATS == 2) {
            #pragma unroll
            for (int i = 0; i < 4; i++) cp16(smb + 2 * TILE_F * 4 + brel[i] + so, b1src[i] + k0, 16);
        }
        cp_commit();
    };

    float acc[NMATS][4][4][4];
    #pragma unroll
    for (int m = 0; m < NMATS; m++)
        #pragma unroll
        for (int a = 0; a < 4; a++)
            #pragma unroll
            for (int b = 0; b < 4; b++)
                #pragma unroll
                for (int c = 0; c < 4; c++) acc[m][a][b][c] = 0.f;

    #pragma unroll
    for (int c = 0; c < S - 1; c++) load_chunk(c);

    const int aoff0 = (wm * 64 + lr) * RS + lc;
    const int boff0 = (wn * 32 + lr) * RS + lc;

    for (int kt = 0; kt < KT; kt++) {
        if (kt + S - 1 < KT) load_chunk(kt + S - 1); else cp_commit();
        cp_wait<S - 1>();
        __syncthreads();

        const float* As  = smf + (kt % S) * STAGE_F;
        const float* Bs0 = As + TILE_F;
        const float* Bs1 = Bs0 + TILE_F;

        #pragma unroll
        for (int kk = 0; kk < 4; kk++) {
            const int k = kk * 8;
            uint32_t a[4][4];
            #pragma unroll
            for (int mt = 0; mt < 4; mt++) {
                const float* p = As + aoff0 + mt * (16 * RS) + k;
                a[mt][0] = __float_as_uint(p[0]);
                a[mt][1] = __float_as_uint(p[8 * RS]);
                a[mt][2] = __float_as_uint(p[4]);
                a[mt][3] = __float_as_uint(p[8 * RS + 4]);
            }
            #pragma unroll
            for (int m = 0; m < NMATS; m++) {
                const float* Bb = (m == 0) ? Bs0 : Bs1;
                #pragma unroll
                for (int nt = 0; nt < 4; nt++) {
                    const float* q = Bb + boff0 + nt * (8 * RS) + k;
                    const uint32_t b0 = __float_as_uint(q[0]);
                    const uint32_t b1 = __float_as_uint(q[4]);
                    #pragma unroll
                    for (int mt = 0; mt < 4; mt++) mma8(acc[m][mt][nt], a[mt], b0, b1);
                }
            }
        }
        __syncthreads();
    }

    // ---- epilogue ----
    #pragma unroll
    for (int mt = 0; mt < 4; mt++) {
        #pragma unroll
        for (int nt = 0; nt < 4; nt++) {
            const int r1 = row0 + wm * 64 + mt * 16 + lr;
            const int cc = n0 + wn * 32 + nt * 8 + lc * 2;
            if (NMATS == 2) {
                const float g0 = acc[0][mt][nt][0], g1 = acc[0][mt][nt][1];
                const float g2 = acc[0][mt][nt][2], g3 = acc[0][mt][nt][3];
                const float u0 = acc[1][mt][nt][0], u1 = acc[1][mt][nt][1];
                const float u2 = acc[1][mt][nt][2], u3 = acc[1][mt][nt][3];
                float2 v0, v1;
                v0.x = tf32r(g0 * u0 / (1.f + expf(-g0)));
                v0.y = tf32r(g1 * u1 / (1.f + expf(-g1)));
                v1.x = tf32r(g2 * u2 / (1.f + expf(-g2)));
                v1.y = tf32r(g3 * u3 / (1.f + expf(-g3)));
                *(float2*)&Outg[(size_t)r1 * NDIM + cc]       = v0;
                *(float2*)&Outg[(size_t)(r1 + 8) * NDIM + cc] = v1;
            } else {
                float2 v0 = make_float2(acc[0][mt][nt][0], acc[0][mt][nt][1]);
                float2 v1 = make_float2(acc[0][mt][nt][2], acc[0][mt][nt][3]);
                *(float2*)&Outg[(size_t)r1 * NDIM + cc]       = v0;
                *(float2*)&Outg[(size_t)(r1 + 8) * NDIM + cc] = v1;
            }
        }
    }
}

// ---------------- combine ----------------
__global__ void moe_combine(float* __restrict__ out) {
    const int t = blockIdx.x;
    const int s0 = g_tok2slot[2 * t];
    const int s1 = g_tok2slot[2 * t + 1];
    const float w0 = g_tokw[2 * t];
    const float w1 = g_tokw[2 * t + 1];
    const float* p0 = g_pout + (size_t)s0 * HDIM;
    const float* p1 = g_pout + (size_t)s1 * HDIM;
    float* o = out + (size_t)t * HDIM;
    #pragma unroll
    for (int i = 0; i < 4; i++) {
        int h = threadIdx.x + i * 256;
        o[h] = w0 * p0[h] + w1 * p1[h];
    }
}

// ---------------- launch ----------------
extern "C" void kernel_launch(void* const* d_in, const int* in_sizes, int n_in,
                              void* d_out, int out_size) {
    const float* x  = (const float*)d_in[0];   // [T, H]
    const float* gw = (const float*)d_in[1];   // [H, E]
    const float* wg = (const float*)d_in[2];   // [E, H, I]
    const float* wu = (const float*)d_in[3];   // [E, H, I]
    const float* wd = (const float*)d_in[4];   // [E, I, H]
    float* out = (float*)d_out;
    const int base = T_TOK * HDIM;

    // smem: stage = (1+NMATS) * 128*36*4 bytes
    const int sm1 = 3 * 3 * 128 * 36 * 4;   // 165888 B (A+B0+B1, 3 stages)
    const int sm2 = 4 * 2 * 128 * 36 * 4;   // 147456 B (A+B0, 4 stages)
    cudaFuncSetAttribute(gemm_mma<2, HDIM, IDIM, 3>,
                         cudaFuncAttributeMaxDynamicSharedMemorySize, sm1);
    cudaFuncSetAttribute(gemm_mma<1, IDIM, HDIM, 4>,
                         cudaFuncAttributeMaxDynamicSharedMemorySize, sm2);

    moe_init<<<1, 256>>>();
    moe_router<<<T_TOK / 8, 256>>>(x, gw);
    moe_sched<<<1, 32>>>(out + base, (out_size > base) ? 1 : 0);
    moe_scatter<<<T_TOK / 256, 256>>>();

    prep_round_x<<<(T_TOK * HDIM) / 1024, 256>>>(x);
    prep_transpose<HDIM, IDIM><<<dim3(IDIM / 32, HDIM / 32, NEXP), dim3(32, 8)>>>(wg, 0);
    prep_transpose<HDIM, IDIM><<<dim3(IDIM / 32, HDIM / 32, NEXP), dim3(32, 8)>>>(wu, 1);
    prep_transpose<IDIM, HDIM><<<dim3(HDIM / 32, IDIM / 32, NEXP), dim3(32, 8)>>>(wd, 2);

    gemm_mma<2, HDIM, IDIM, 3><<<dim3(IDIM / 128, MAXMB), 256, sm1>>>();
    gemm_mma<1, IDIM, HDIM, 4><<<dim3(HDIM / 128, MAXMB), 256, sm2>>>();

    moe_combine<<<T_TOK, 256>>>(out);
}

// round 11
// speedup vs baseline: 1.6294x; 1.6294x over previous
#include <cuda_runtime.h>
#include <cuda_fp16.h>
#include <math.h>
#include <stdint.h>

// Problem constants
#define T_TOK   4096      // B*S = 2*2048
#define HDIM    1024
#define IDIM    4096
#define NEXP    8
#define MAXSLOT 9216      // 8192 pairs + per-expert pad to 128
#define MAXMB   72        // max m-blocks of 128 rows

// ---------------- static scratch (no runtime allocation) ----------------
__device__ __align__(16) __half g_hdn[(size_t)MAXSLOT * IDIM];      // 75.5 MB (fp16)
__device__ float  g_pout[(size_t)MAXSLOT * HDIM];                   // 37.7 MB
__device__ __align__(16) __half g_xh [(size_t)T_TOK * HDIM];        // 8.4 MB  fp16 x
__device__ __align__(16) __half g_wgT[(size_t)NEXP * HDIM * IDIM];  // 67 MB  wg^T [E][I][H]
__device__ __align__(16) __half g_wuT[(size_t)NEXP * HDIM * IDIM];  // 67 MB  wu^T [E][I][H]
__device__ __align__(16) __half g_wdT[(size_t)NEXP * HDIM * IDIM];  // 67 MB  wd^T [E][H][I]
__device__ int   g_perm[MAXSLOT];                                   // slot -> token (-1 = pad)
__device__ int   g_tok2slot[T_TOK * 2];
__device__ float g_tokw   [T_TOK * 2];
__device__ int   g_tokidx [T_TOK * 2];
__device__ int   g_counts [NEXP];
__device__ float g_load   [NEXP];
__device__ int   g_cursor [NEXP];
__device__ int   g_off    [NEXP];
__device__ int2  g_mblocks[80];
__device__ int   g_nmblocks;

// ---------------- PTX helpers ----------------
__device__ __forceinline__ void mma16(float* d, const uint32_t* a, uint32_t b0, uint32_t b1) {
    asm volatile(
        "mma.sync.aligned.m16n8k16.row.col.f32.f16.f16.f32 "
        "{%0,%1,%2,%3}, {%4,%5,%6,%7}, {%8,%9}, {%0,%1,%2,%3};\n"
        : "+f"(d[0]), "+f"(d[1]), "+f"(d[2]), "+f"(d[3])
        : "r"(a[0]), "r"(a[1]), "r"(a[2]), "r"(a[3]), "r"(b0), "r"(b1));
}

__device__ __forceinline__ void cp16(uint32_t dst, const void* src, int bytes) {
    asm volatile("cp.async.cg.shared.global [%0], [%1], 16, %2;\n"
                 :: "r"(dst), "l"(src), "r"(bytes));
}
__device__ __forceinline__ void cp_commit() { asm volatile("cp.async.commit_group;\n"); }
template <int N>
__device__ __forceinline__ void cp_wait() { asm volatile("cp.async.wait_group %0;\n" :: "n"(N)); }

// ---------------- kernel 1: init ----------------
__global__ void moe_init() {
    int tid = threadIdx.x;
    for (int i = tid; i < MAXSLOT; i += 256) g_perm[i] = -1;
    if (tid < NEXP) { g_counts[tid] = 0; g_load[tid] = 0.f; g_cursor[tid] = 0; }
}

// ---------------- kernel 2: router (exact fp32) ----------------
__global__ void moe_router(const float* __restrict__ x, const float* __restrict__ gw) {
    const int warp = threadIdx.x >> 5;
    const int lane = threadIdx.x & 31;
    const int t = blockIdx.x * 8 + warp;

    const int e   = lane & 7;
    const int seg = lane >> 3;
    const float* xr  = x  + (size_t)t * HDIM + seg * 256;
    const float* gwp = gw + (size_t)(seg * 256) * NEXP + e;
    float acc = 0.f;
    #pragma unroll 8
    for (int j = 0; j < 256; j++) acc += xr[j] * gwp[j * NEXP];
    acc += __shfl_xor_sync(0xffffffffu, acc, 8);
    acc += __shfl_xor_sync(0xffffffffu, acc, 16);

    float lg[8];
    #pragma unroll
    for (int i = 0; i < 8; i++) lg[i] = __shfl_sync(0xffffffffu, acc, i);

    if (lane == 0) {
        float m = lg[0];
        #pragma unroll
        for (int i = 1; i < 8; i++) m = fmaxf(m, lg[i]);
        float p[8], s = 0.f;
        #pragma unroll
        for (int i = 0; i < 8; i++) { p[i] = expf(lg[i] - m); s += p[i]; }
        float inv = 1.f / s;
        #pragma unroll
        for (int i = 0; i < 8; i++) p[i] *= inv;
        int i1 = 0;
        #pragma unroll
        for (int i = 1; i < 8; i++) if (p[i] > p[i1]) i1 = i;
        int i2 = (i1 == 0) ? 1 : 0;
        #pragma unroll
        for (int i = 0; i < 8; i++) if (i != i1 && p[i] > p[i2]) i2 = i;
        float denom = p[i1] + p[i2];
        g_tokidx[2 * t]     = i1;
        g_tokidx[2 * t + 1] = i2;
        g_tokw[2 * t]       = p[i1] / denom;
        g_tokw[2 * t + 1]   = p[i2] / denom;
        atomicAdd(&g_counts[i1], 1);
        atomicAdd(&g_counts[i2], 1);
        atomicAdd(&g_load[i1], p[i1]);
        atomicAdd(&g_load[i2], p[i2]);
    }
}

// ---------------- kernel 3: scheduler + aux loss ----------------
__global__ void moe_sched(float* aux_out, int has_aux) {
    if (threadIdx.x == 0) {
        int off = 0, nm = 0;
        for (int e = 0; e < NEXP; e++) {
            g_off[e] = off;
            int nb = (g_counts[e] + 127) >> 7;
            for (int b = 0; b < nb; b++) g_mblocks[nm++] = make_int2(off + b * 128, e);
            off += nb << 7;
        }
        g_nmblocks = nm;
        if (has_aux) {
            float aux = 0.f;
            for (int e = 0; e < NEXP; e++)
                aux += (g_load[e] / (float)T_TOK) * ((float)g_counts[e] / (float)(T_TOK * 2));
            *aux_out = aux * (float)NEXP * 0.001f;
        }
    }
}

// ---------------- kernel 4: scatter ----------------
__global__ void moe_scatter() {
    int t = blockIdx.x * 256 + threadIdx.x;
    if (t < T_TOK) {
        #pragma unroll
        for (int k = 0; k < 2; k++) {
            int e = g_tokidx[2 * t + k];
            int pos = atomicAdd(&g_cursor[e], 1);
            int slot = g_off[e] + pos;
            g_perm[slot] = t;
            g_tok2slot[2 * t + k] = slot;
        }
    }
}

// ---------------- prep: x -> fp16 ----------------
__global__ void prep_half_x(const float* __restrict__ x) {
    size_t i = (size_t)blockIdx.x * 1024 + threadIdx.x * 4;
    float4 v = *(const float4*)(x + i);
    __half2 h01 = __floats2half2_rn(v.x, v.y);
    __half2 h23 = __floats2half2_rn(v.z, v.w);
    *(__half2*)(g_xh + i)     = h01;
    *(__half2*)(g_xh + i + 2) = h23;
}

// ---------------- prep: transpose + convert weights to fp16 ----------------
// in [E][R][C] fp32 -> g_w?T [E][C][R] fp16.  which: 0->wgT, 1->wuT, 2->wdT
template <int R, int C>
__global__ void prep_transpose(const float* __restrict__ in, int which) {
    __shared__ float tile[32][33];
    __half* outg = (which == 0) ? g_wgT : (which == 1) ? g_wuT : g_wdT;
    const int e = blockIdx.z;
    const float* ip = in + (size_t)e * R * C;
    __half* op = outg + (size_t)e * R * C;
    const int x = blockIdx.x * 32 + threadIdx.x;
    const int y0 = blockIdx.y * 32;
    #pragma unroll
    for (int j = threadIdx.y; j < 32; j += 8)
        tile[j][threadIdx.x] = ip[(size_t)(y0 + j) * C + x];
    __syncthreads();
    const int x2 = y0 + threadIdx.x;
    const int y2 = blockIdx.x * 32;
    #pragma unroll
    for (int j = threadIdx.y; j < 32; j += 8)
        op[(size_t)(y2 + j) * R + x2] = __float2half_rn(tile[threadIdx.x][j]);
}

// ---------------- fp16 legacy-mma GEMM ----------------
// NMATS==2: A = g_xh gathered via g_perm; B0/B1 = g_wgT/g_wuT [N][K]; out = half(silu(g)*u) -> g_hdn
// NMATS==1: A = g_hdn slot rows;          B0 = g_wdT [N][K];          out -> g_pout (fp32)
// CTA 128(M) x 128(N per matrix), BK=32, 256 threads, warp tile 64x32.
// Smem tiles 128x32 half = 8192 B, XOR-swizzled (chunk ^ ((row>>1)&3)), S-stage cp.async.
template <int NMATS, int KDIM, int NDIM, int S>
__global__ void __launch_bounds__(256, 1)
gemm_fp16()
{
    constexpr int TILE_B  = 128 * 64;            // bytes per 128x32-half tile
    constexpr int STAGE_B = (1 + NMATS) * TILE_B;
    constexpr int KT = KDIM / 32;

    const int mb = blockIdx.y;
    if (mb >= g_nmblocks) return;
    const int row0 = g_mblocks[mb].x;
    const int e    = g_mblocks[mb].y;
    const int n0   = blockIdx.x * 128;

    const __half* B0 = ((NMATS == 2) ? g_wgT : g_wdT) + (size_t)e * KDIM * NDIM;
    const __half* B1 = g_wuT + (size_t)e * KDIM * NDIM;   // only when NMATS==2

    extern __shared__ char smem[];
    const uint32_t smb = (uint32_t)__cvta_generic_to_shared(smem);

    const int tid  = threadIdx.x;
    const int lane = tid & 31;
    const int wid  = tid >> 5;
    const int wm = wid & 1;      // M half (64 rows)
    const int wn = wid >> 1;     // N quarter (32 cols)
    const int lr = lane >> 2;    // 0..7
    const int lc = lane & 3;     // 0..3

    // ---- loaders: 2 x 16B chunks per thread per 128x32 tile ----
    uint32_t drel[2]; const __half* asrc[2]; int alen[2];
    const __half* b0src[2]; const __half* b1src[2];
    #pragma unroll
    for (int i = 0; i < 2; i++) {
        const int cid = tid + 256 * i;
        const int r = cid >> 2;           // 0..127
        const int c = cid & 3;            // 16B chunk (8 halves) within 32-half row
        drel[i] = (uint32_t)(r * 64 + ((c ^ ((r >> 1) & 3)) * 16));
        if (NMATS == 2) {
            const int g = g_perm[row0 + r];
            asrc[i] = (g >= 0) ? (g_xh + (size_t)g * KDIM + c * 8) : g_xh;
            alen[i] = (g >= 0) ? 16 : 0;
        } else {
            asrc[i] = g_hdn + (size_t)(row0 + r) * KDIM + c * 8;
            alen[i] = 16;
        }
        b0src[i] = B0 + (size_t)(n0 + r) * KDIM + c * 8;
        if (NMATS == 2) b1src[i] = B1 + (size_t)(n0 + r) * KDIM + c * 8;
    }

    auto load_chunk = [&](int ch) {
        const uint32_t so = smb + (uint32_t)((ch % S) * STAGE_B);
        const int k0 = ch * 32;
        #pragma unroll
        for (int i = 0; i < 2; i++) cp16(so + drel[i], asrc[i] + k0, alen[i]);
        #pragma unroll
        for (int i = 0; i < 2; i++) cp16(so + TILE_B + drel[i], b0src[i] + k0, 16);
        if (NMATS == 2) {
            #pragma unroll
            for (int i = 0; i < 2; i++) cp16(so + 2 * TILE_B + drel[i], b1src[i] + k0, 16);
        }
        cp_commit();
    };

    float acc[NMATS][4][4][4];
    #pragma unroll
    for (int m = 0; m < NMATS; m++)
        #pragma unroll
        for (int a = 0; a < 4; a++)
            #pragma unroll
            for (int b = 0; b < 4; b++)
                #pragma unroll
                for (int c = 0; c < 4; c++) acc[m][a][b][c] = 0.f;

    #pragma unroll
    for (int c = 0; c < S - 1; c++) load_chunk(c);

    const int f     = (lr >> 1) & 3;          // swizzle constant per thread
    const int abase = (wm * 64 + lr) * 64 + lc * 4;
    const int bbase = (wn * 32 + lr) * 64 + lc * 4;

    for (int kt = 0; kt < KT; kt++) {
        if (kt + S - 1 < KT) load_chunk(kt + S - 1); else cp_commit();
        cp_wait<S - 1>();
        __syncthreads();

        const char* stg = smem + (size_t)(kt % S) * STAGE_B;
        const char* Bs0 = stg + TILE_B;
        const char* Bs1 = stg + 2 * TILE_B;

        #pragma unroll
        for (int kk = 0; kk < 2; kk++) {           // two k16 steps per 32-K chunk
            const int c0 = ((2 * kk) ^ f) * 16;
            const int c1 = ((2 * kk + 1) ^ f) * 16;
            uint32_t a[4][4];
            #pragma unroll
            for (int mt = 0; mt < 4; mt++) {
                const char* p = stg + abase + mt * (16 * 64);
                a[mt][0] = *(const uint32_t*)(p + c0);
                a[mt][1] = *(const uint32_t*)(p + 512 + c0);
                a[mt][2] = *(const uint32_t*)(p + c1);
                a[mt][3] = *(const uint32_t*)(p + 512 + c1);
            }
            #pragma unroll
            for (int m = 0; m < NMATS; m++) {
                const char* Bb = (m == 0) ? Bs0 : Bs1;
                #pragma unroll
                for (int nt = 0; nt < 4; nt++) {
                    const char* q = Bb + bbase + nt * (8 * 64);
                    const uint32_t b0 = *(const uint32_t*)(q + c0);
                    const uint32_t b1 = *(const uint32_t*)(q + c1);
                    #pragma unroll
                    for (int mt = 0; mt < 4; mt++) mma16(acc[m][mt][nt], a[mt], b0, b1);
                }
            }
        }
        __syncthreads();
    }

    // ---- epilogue ----
    #pragma unroll
    for (int mt = 0; mt < 4; mt++) {
        #pragma unroll
        for (int nt = 0; nt < 4; nt++) {
            const int r1 = row0 + wm * 64 + mt * 16 + lr;
            const int cc = n0 + wn * 32 + nt * 8 + lc * 2;
            if (NMATS == 2) {
                const float g0 = acc[0][mt][nt][0], g1 = acc[0][mt][nt][1];
                const float g2 = acc[0][mt][nt][2], g3 = acc[0][mt][nt][3];
                const float u0 = acc[1][mt][nt][0], u1 = acc[1][mt][nt][1];
                const float u2 = acc[1][mt][nt][2], u3 = acc[1][mt][nt][3];
                const float v0 = g0 * u0 / (1.f + expf(-g0));
                const float v1 = g1 * u1 / (1.f + expf(-g1));
                const float v2 = g2 * u2 / (1.f + expf(-g2));
                const float v3 = g3 * u3 / (1.f + expf(-g3));
                *(__half2*)&g_hdn[(size_t)r1 * IDIM + cc]       = __floats2half2_rn(v0, v1);
                *(__half2*)&g_hdn[(size_t)(r1 + 8) * IDIM + cc] = __floats2half2_rn(v2, v3);
            } else {
                float2 w0 = make_float2(acc[0][mt][nt][0], acc[0][mt][nt][1]);
                float2 w1 = make_float2(acc[0][mt][nt][2], acc[0][mt][nt][3]);
                *(float2*)&g_pout[(size_t)r1 * HDIM + cc]       = w0;
                *(float2*)&g_pout[(size_t)(r1 + 8) * HDIM + cc] = w1;
            }
        }
    }
}

// ---------------- combine ----------------
__global__ void moe_combine(float* __restrict__ out) {
    const int t = blockIdx.x;
    const int s0 = g_tok2slot[2 * t];
    const int s1 = g_tok2slot[2 * t + 1];
    const float w0 = g_tokw[2 * t];
    const float w1 = g_tokw[2 * t + 1];
    const float* p0 = g_pout + (size_t)s0 * HDIM;
    const float* p1 = g_pout + (size_t)s1 * HDIM;
    float* o = out + (size_t)t * HDIM;
    #pragma unroll
    for (int i = 0; i < 4; i++) {
        int h = threadIdx.x + i * 256;
        o[h] = w0 * p0[h] + w1 * p1[h];
    }
}

// ---------------- launch ----------------
extern "C" void kernel_launch(void* const* d_in, const int* in_sizes, int n_in,
                              void* d_out, int out_size) {
    const float* x  = (const float*)d_in[0];   // [T, H]
    const float* gw = (const float*)d_in[1];   // [H, E]
    const float* wg = (const float*)d_in[2];   // [E, H, I]
    const float* wu = (const float*)d_in[3];   // [E, H, I]
    const float* wd = (const float*)d_in[4];   // [E, I, H]
    float* out = (float*)d_out;
    const int base = T_TOK * HDIM;

    const int sm1 = 5 * 3 * 8192;   // 122880 B (A+B0+B1, 5 stages)
    const int sm2 = 6 * 2 * 8192;   //  98304 B (A+B0, 6 stages)
    cudaFuncSetAttribute(gemm_fp16<2, HDIM, IDIM, 5>,
                         cudaFuncAttributeMaxDynamicSharedMemorySize, sm1);
    cudaFuncSetAttribute(gemm_fp16<1, IDIM, HDIM, 6>,
                         cudaFuncAttributeMaxDynamicSharedMemorySize, sm2);

    moe_init<<<1, 256>>>();
    moe_router<<<T_TOK / 8, 256>>>(x, gw);
    moe_sched<<<1, 32>>>(out + base, (out_size > base) ? 1 : 0);
    moe_scatter<<<T_TOK / 256, 256>>>();

    prep_half_x<<<(T_TOK * HDIM) / 1024, 256>>>(x);
    prep_transpose<HDIM, IDIM><<<dim3(IDIM / 32, HDIM / 32, NEXP), dim3(32, 8)>>>(wg, 0);
    prep_transpose<HDIM, IDIM><<<dim3(IDIM / 32, HDIM / 32, NEXP), dim3(32, 8)>>>(wu, 1);
    prep_transpose<IDIM, HDIM><<<dim3(HDIM / 32, IDIM / 32, NEXP), dim3(32, 8)>>>(wd, 2);

    gemm_fp16<2, HDIM, IDIM, 5><<<dim3(IDIM / 128, MAXMB), 256, sm1>>>();
    gemm_fp16<1, IDIM, HDIM, 6><<<dim3(HDIM / 128, MAXMB), 256, sm2>>>();

    moe_combine<<<T_TOK, 256>>>(out);
}